// round 17
// baseline (speedup 1.0000x reference)
#include <cuda_runtime.h>
#include <cuda_fp16.h>
#include <math.h>
#include <stdint.h>

#define BATCH 4
#define LSEQ 2048
#define DMODEL 1024
#define NHEADS 8
#define DHEAD 128
#define MROWS (BATCH*LSEQ)

// ---------------- device scratch --------------------------------------------
__device__ __half g_Wt[5120*1024];                // transposed weights [n][k] fp16
__device__ __half g_Xr[MROWS*DMODEL];             // fp16 X
__device__ __half g_Q [BATCH*NHEADS*LSEQ*DHEAD];  // [b,h,l,e]
__device__ __half g_K [BATCH*NHEADS*LSEQ*DHEAD];
__device__ __half g_Vt[BATCH*NHEADS*DHEAD*LSEQ];  // [b,h,v,l]
__device__ float  g_G [MROWS*DMODEL];             // raw gate GEMM output f32
__device__ __half g_Sx[MROWS*DMODEL];             // silu(G)*Yn fp16
__device__ float g_qc[LSEQ*64];
__device__ float g_qs[LSEQ*64];
__device__ float g_kc[LSEQ*64];
__device__ float g_ks[LSEQ*64];
__device__ float g_pn[NHEADS*LSEQ];               // gamma^l
__device__ float g_pm[NHEADS*LSEQ];               // gamma^-l
__device__ int   g_win[NHEADS];                   // decay window (elements)

// ---------------- helpers ----------------------------------------------------
__device__ __forceinline__ uint32_t smem_u32(const void* p) {
    uint32_t a;
    asm("{ .reg .u64 t; cvta.to.shared.u64 t, %1; cvt.u32.u64 %0, t; }" : "=r"(a) : "l"(p));
    return a;
}
__device__ __forceinline__ void mma16(float d[4], uint32_t a0, uint32_t a1, uint32_t a2, uint32_t a3,
                                      uint32_t b0, uint32_t b1) {
    asm volatile(
        "mma.sync.aligned.m16n8k16.row.col.f32.f16.f16.f32 "
        "{%0,%1,%2,%3}, {%4,%5,%6,%7}, {%8,%9}, {%0,%1,%2,%3};"
        : "+f"(d[0]), "+f"(d[1]), "+f"(d[2]), "+f"(d[3])
        : "r"(a0), "r"(a1), "r"(a2), "r"(a3), "r"(b0), "r"(b1));
}
#define LDU(p) (*(const uint32_t*)(p))
#define CP16(dst, src)  asm volatile("cp.async.cg.shared.global [%0], [%1], 16;" :: "r"(dst), "l"(src) : "memory")
#define CPCOMMIT()      asm volatile("cp.async.commit_group;" ::: "memory")
#define CPWAIT0()       asm volatile("cp.async.wait_group 0;" ::: "memory")
#define CPWAIT1()       asm volatile("cp.async.wait_group 1;" ::: "memory")

// ---------------- merged prep: tables + X->fp16 ------------------------------
__global__ void prep_kernel(const float* __restrict__ X) {
    int idx = blockIdx.x*blockDim.x + threadIdx.x;
    {
        float4 v0 = ((const float4*)X)[idx*2];
        float4 v1 = ((const float4*)X)[idx*2 + 1];
        __half2 h[4];
        h[0] = __floats2half2_rn(v0.x, v0.y);
        h[1] = __floats2half2_rn(v0.z, v0.w);
        h[2] = __floats2half2_rn(v1.x, v1.y);
        h[3] = __floats2half2_rn(v1.z, v1.w);
        *(uint4*)(g_Xr + (size_t)idx*8) = *(uint4*)h;
    }
    if (idx < LSEQ*64) {
        int l = idx >> 6, j = idx & 63;
        float dh = (float)DHEAD;
        float base = (2.f*(float)j + 0.4f*dh) / (1.4f*dh);
        float scale = powf(base, (float)l / 512.0f);
        float inv_freq = powf(10000.0f, -(float)j / 64.0f);
        float arg = (float)l * inv_freq;
        float sv = sinf(arg), cv = cosf(arg);
        g_qc[idx] = cv * scale;
        g_qs[idx] = sv * scale;
        float iscale = 1.0f / scale;
        g_kc[idx] = cv * iscale;
        g_ks[idx] = sv * iscale;
    }
    if (idx < NHEADS*LSEQ) {
        int h = idx >> 11, k = idx & (LSEQ-1);
        float lg0 = logf(1.0f/32.0f), lg1 = logf(1.0f/512.0f);
        float lg = lg0 + (lg1 - lg0) * ((float)h / (float)(NHEADS-1));
        float gamma = 1.0f - expf(lg);
        double lng = (double)logf(gamma);
        g_pn[idx] = (float)exp((double)k * lng);
        g_pm[idx] = (float)exp(-(double)k * lng);
        if (k == 0) {
            double W = 11.512925 / (-lng);
            g_win[h] = (W >= 2047.0) ? 2047 : (int)W;
        }
    }
}

// ---------------- weight transpose -> fp16 ----------------------------------
__global__ void wtrans_kernel(const float* __restrict__ WQ, const float* __restrict__ WK,
                              const float* __restrict__ WV, const float* __restrict__ WG,
                              const float* __restrict__ WO) {
    __shared__ float t[32][33];
    int kT = blockIdx.x << 5, nT = blockIdx.y << 5;
    int tx = threadIdx.x, ty = threadIdx.y;   // 32 x 8
    #pragma unroll
    for (int r = 0; r < 4; r++) {
        int n = nT + tx, k = kT + ty + 8*r;
        float v;
        if (n < 3072) {
            int sel = n >> 10, h = (n >> 7) & 7, e = n & 127;
            const float* W = (sel == 0) ? WQ : (sel == 1) ? WK : WV;
            v = W[(size_t)h*131072 + (size_t)k*128 + e];
        } else if (n < 4096) {
            v = WG[(size_t)k*1024 + (n - 3072)];
        } else {
            v = WO[(size_t)k*1024 + (n - 4096)];
        }
        t[ty + 8*r][tx] = v;
    }
    __syncthreads();
    #pragma unroll
    for (int r = 0; r < 4; r++) {
        int n = nT + ty + 8*r, k = kT + tx;
        g_Wt[(size_t)n*1024 + k] = __float2half(t[tx][ty + 8*r]);
    }
}

// ---------------- unified fp16 mma GEMM: 3-stage, 1 barrier/chunk ------------
#define MM_SMEM (110592)
__global__ __launch_bounds__(256) void mm_kernel(float* __restrict__ Cout, int mode, int wRowOff) {
    extern __shared__ __half smh[];
    const int tid = threadIdx.x;
    const int wid = tid >> 5, lane = tid & 31;
    const int q = lane >> 2, tq = lane & 3;
    const int wm = wid & 3, wn = wid >> 2;
    const int rb = blockIdx.y << 7, cb = blockIdx.x << 7;

    const __half* Ap = ((mode == 2) ? g_Sx : g_Xr) + (size_t)rb * 1024;
    const __half* Bp = g_Wt + (size_t)(wRowOff + cb) * 1024;

    uint32_t smb = smem_u32(smh);
    auto issue_chunk = [&](int kc, int s) {
        int kt = kc * 64;
        uint32_t ab = smb + (uint32_t)s * 18432u;
        uint32_t bb = smb + 55296u + (uint32_t)s * 18432u;
        #pragma unroll
        for (int i = 0; i < 4; i++) {
            int ch = tid + (i << 8);
            int r = ch >> 3, c8 = (ch & 7) << 3;
            CP16(ab + (uint32_t)(r*72 + c8)*2u, Ap + (size_t)r*1024 + kt + c8);
            CP16(bb + (uint32_t)(r*72 + c8)*2u, Bp + (size_t)r*1024 + kt + c8);
        }
        CPCOMMIT();
    };

    float acc[2][8][4];
    #pragma unroll
    for (int mi = 0; mi < 2; mi++)
        #pragma unroll
        for (int ni = 0; ni < 8; ni++)
            #pragma unroll
            for (int c = 0; c < 4; c++) acc[mi][ni][c] = 0.0f;

    issue_chunk(0, 0);
    issue_chunk(1, 1);

    #pragma unroll 1
    for (int k = 0; k < 16; k++) {
        int s = k % 3;
        if (k + 2 < 16) CPWAIT1(); else CPWAIT0();
        __syncthreads();
        if (k + 2 < 16) issue_chunk(k + 2, (k + 2) % 3);

        const __half* A_ = smh + s * 9216;
        const __half* B_ = smh + 27648 + s * 9216;
        #pragma unroll
        for (int ks = 0; ks < 4; ks++) {
            int c = ks*16 + 2*tq;
            uint32_t af[2][4];
            uint32_t bf[8][2];
            #pragma unroll
            for (int mi = 0; mi < 2; mi++) {
                int r = wm*32 + mi*16 + q;
                af[mi][0] = LDU(A_ + r*72 + c);
                af[mi][1] = LDU(A_ + (r+8)*72 + c);
                af[mi][2] = LDU(A_ + r*72 + c + 8);
                af[mi][3] = LDU(A_ + (r+8)*72 + c + 8);
            }
            #pragma unroll
            for (int ni = 0; ni < 8; ni++) {
                int n = wn*64 + ni*8 + q;
                bf[ni][0] = LDU(B_ + n*72 + c);
                bf[ni][1] = LDU(B_ + n*72 + c + 8);
            }
            #pragma unroll
            for (int ni = 0; ni < 8; ni++) {
                mma16(acc[0][ni], af[0][0], af[0][1], af[0][2], af[0][3], bf[ni][0], bf[ni][1]);
                mma16(acc[1][ni], af[1][0], af[1][1], af[1][2], af[1][3], bf[ni][0], bf[ni][1]);
            }
        }
    }

    // ---------------- epilogue ----------------
    int sel = 0, hh = 0;
    if (mode == 0) { sel = blockIdx.x >> 3; hh = blockIdx.x & 7; }

    #pragma unroll
    for (int mi = 0; mi < 2; mi++) {
        #pragma unroll
        for (int half_ = 0; half_ < 2; half_++) {
            int row = rb + wm*32 + mi*16 + q + half_*8;
            int bb = row >> 11, l = row & (LSEQ - 1);
            #pragma unroll
            for (int ni = 0; ni < 8; ni++) {
                int colb = wn*64 + ni*8 + 2*tq;
                float x1 = acc[mi][ni][half_*2 + 0];
                float x2 = acc[mi][ni][half_*2 + 1];
                if (mode == 0) {
                    size_t hbase = (size_t)(bb*NHEADS + hh);
                    if (sel == 3) {
                        size_t off = (size_t)row*1024 + (cb - 3072) + colb;
                        *(float2*)(g_G + off) = make_float2(x1, x2);
                    } else if (sel == 2) {
                        __half* vt = g_Vt + hbase * (size_t)(DHEAD*LSEQ);
                        vt[(size_t)colb * LSEQ + l]       = __float2half(x1);
                        vt[(size_t)(colb + 1) * LSEQ + l] = __float2half(x2);
                    } else {
                        const float* ct = (sel == 0) ? g_qc : g_kc;
                        const float* st = (sel == 0) ? g_qs : g_ks;
                        int jj = colb >> 1;
                        float cv = ct[l*64 + jj], sv = st[l*64 + jj];
                        __half2 o = __floats2half2_rn(x1*cv - x2*sv, x2*cv + x1*sv);
                        __half* dst = ((sel == 0) ? g_Q : g_K) + (hbase*LSEQ + l)*DHEAD + colb;
                        *(__half2*)dst = o;
                    }
                } else {
                    size_t off = (size_t)row*1024 + cb + colb;
                    *(float2*)(Cout + off) = make_float2(x1, x2);
                }
            }
        }
    }
}

// ---------------- attention v3: FA2-style fragment reuse ---------------------
// 8 warps x 16 rows; S stays in registers (C-frag -> A-frag pack).
// smem halves: Qs[128][136] | Ks[2][64][136] | Vs[2][128][72] = 104 KB, 2 CTA/SM
#define QS_O  0
#define KS0_O 17408
#define KS1_O 26112
#define VS0_O 34816
#define VS1_O 44032
#define ATT_SMEM (53248*2)
__global__ __launch_bounds__(256, 2) void attn_kernel(
    const float* __restrict__ gw, const float* __restrict__ gb)
{
    extern __shared__ __half smh[];
    __half* Qs = smh + QS_O;
    __half* Ks[2] = { smh + KS0_O, smh + KS1_O };
    __half* Vs[2] = { smh + VS0_O, smh + VS1_O };
    uint32_t smb = smem_u32(smh);
    uint32_t qsb = smb + QS_O*2u;
    uint32_t ksb[2] = { smb + KS0_O*2u, smb + KS1_O*2u };
    uint32_t vsb[2] = { smb + VS0_O*2u, smb + VS1_O*2u };

    const int tid = threadIdx.x;
    const int wid = tid >> 5, lane = tid & 31;
    const int q = lane >> 2, tq = lane & 3;
    const int r0 = wid * 16;

    int nt = (int)(gridDim.x - 1) - (int)blockIdx.x;   // big tiles first
    int h = blockIdx.y, b = blockIdx.z;
    int nb = nt << 7;

    size_t hb = (size_t)(b*NHEADS + h);
    const __half* Qg = g_Q + hb * (size_t)(LSEQ*DHEAD);
    const __half* Kg = g_K + hb * (size_t)(LSEQ*DHEAD);
    const __half* Vg = g_Vt + hb * (size_t)(DHEAD*LSEQ);
    const float* pm = g_pm + h*LSEQ;

    int nMt = 2*nt + 2;
    int mt0 = (nb - g_win[h]) >> 6;
    if (mt0 < 0) mt0 = 0;

    const int n0 = nb + r0 + q, n1 = n0 + 8;
    const float pn0 = g_pn[h*LSEQ + n0];
    const float pn1 = g_pn[h*LSEQ + n1];

    // prologue: Q (8 cp16/thr) + K[mt0] (4/thr) + V[mt0] (4/thr), one group
    {
        int r = tid >> 1, part = (tid & 1) * 64;
        const __half* src = Qg + (size_t)(nb + r)*DHEAD + part;
        #pragma unroll
        for (int i = 0; i < 8; i++)
            CP16(qsb + (uint32_t)(r*136 + part + i*8)*2u, src + i*8);
        int kr = tid >> 2, kc = (tid & 3) * 32;
        const __half* ksrc = Kg + (size_t)(mt0*64 + kr)*DHEAD + kc;
        #pragma unroll
        for (int i = 0; i < 4; i++)
            CP16(ksb[0] + (uint32_t)(kr*136 + kc + i*8)*2u, ksrc + i*8);
        int vr = tid >> 1, vc = (tid & 1) * 32;
        const __half* vsrc = Vg + (size_t)vr*LSEQ + mt0*64 + vc;
        #pragma unroll
        for (int i = 0; i < 4; i++)
            CP16(vsb[0] + (uint32_t)(vr*72 + vc + i*8)*2u, vsrc + i*8);
        CPCOMMIT();
    }

    float yacc[16][4];
    #pragma unroll
    for (int ni = 0; ni < 16; ni++)
        #pragma unroll
        for (int c = 0; c < 4; c++) yacc[ni][c] = 0.0f;

    #pragma unroll 1
    for (int mt = mt0; mt < nMt; mt++) {
        int mb_ = mt << 6;
        int buf = (mt - mt0) & 1;
        CPWAIT0();              // K[mt] + V[mt] resident
        __syncthreads();        // all warps done step mt-1 (read buf^1)

        // issue K[mt+1] + V[mt+1] into other buffers (hidden under S+Y)
        if (mt + 1 < nMt) {
            int kr = tid >> 2, kc = (tid & 3) * 32;
            const __half* ksrc = Kg + (size_t)(mb_ + 64 + kr)*DHEAD + kc;
            #pragma unroll
            for (int i = 0; i < 4; i++)
                CP16(ksb[buf^1] + (uint32_t)(kr*136 + kc + i*8)*2u, ksrc + i*8);
            int vr = tid >> 1, vc = (tid & 1) * 32;
            const __half* vsrc = Vg + (size_t)vr*LSEQ + mb_ + 64 + vc;
            #pragma unroll
            for (int i = 0; i < 4; i++)
                CP16(vsb[buf^1] + (uint32_t)(vr*72 + vc + i*8)*2u, vsrc + i*8);
            CPCOMMIT();
        }

        const __half* K_ = Ks[buf];
        // S = Q K^T : warp tile 16 rows x 64 cols, k-depth 128 (8 k16 steps)
        float sacc[8][4];
        #pragma unroll
        for (int nj = 0; nj < 8; nj++)
            #pragma unroll
            for (int c = 0; c < 4; c++) sacc[nj][c] = 0.0f;
        #pragma unroll
        for (int ks = 0; ks < 8; ks++) {
            int c = ks*16 + 2*tq;
            uint32_t a0 = LDU(Qs + (r0+q)*136 + c);
            uint32_t a1 = LDU(Qs + (r0+q+8)*136 + c);
            uint32_t a2 = LDU(Qs + (r0+q)*136 + c + 8);
            uint32_t a3 = LDU(Qs + (r0+q+8)*136 + c + 8);
            #pragma unroll
            for (int nj = 0; nj < 8; nj++) {
                int m = nj*8 + q;
                uint32_t b0 = LDU(K_ + m*136 + c);
                uint32_t b1 = LDU(K_ + m*136 + c + 8);
                mma16(sacc[nj], a0, a1, a2, a3, b0, b1);
            }
        }

        // decay + pack S C-frags into Y A-frags (registers only)
        uint32_t pa[4][4];
        const float* pmp = pm + mb_;
        #pragma unroll
        for (int kt = 0; kt < 4; kt++) {
            #pragma unroll
            for (int jj = 0; jj < 2; jj++) {
                int nj = 2*kt + jj;
                int m = nj*8 + 2*tq;
                int mg = mb_ + m;
                float2 ip = *(const float2*)(pmp + m);
                float d0 = (n0 >= mg) ? sacc[nj][0] * (pn0*ip.x) : 0.0f;
                float d1 = (n0 >  mg) ? sacc[nj][1] * (pn0*ip.y) : 0.0f;
                float d2 = (n1 >= mg) ? sacc[nj][2] * (pn1*ip.x) : 0.0f;
                float d3 = (n1 >  mg) ? sacc[nj][3] * (pn1*ip.y) : 0.0f;
                __half2 p01 = __floats2half2_rn(d0, d1);
                __half2 p23 = __floats2half2_rn(d2, d3);
                pa[kt][jj*2 + 0] = *(uint32_t*)&p01;
                pa[kt][jj*2 + 1] = *(uint32_t*)&p23;
            }
        }

        const __half* V_ = Vs[buf];
        // Y += S V^T : warp tile 16 rows x 128 cols, k-depth 64 (4 k16 steps)
        #pragma unroll
        for (int kt = 0; kt < 4; kt++) {
            int c = kt*16 + 2*tq;
            #pragma unroll
            for (int ni = 0; ni < 16; ni++) {
                int v = ni*8 + q;
                uint32_t b0 = LDU(V_ + v*72 + c);
                uint32_t b1 = LDU(V_ + v*72 + c + 8);
                mma16(yacc[ni], pa[kt][0], pa[kt][1], pa[kt][2], pa[kt][3], b0, b1);
            }
        }
    }

    // -------- warp-local group norm + gate: Sx = silu(G)*(gn(Y)*gw+gb) -------
    float s0 = 0.0f, ss0 = 0.0f, s1 = 0.0f, ss1 = 0.0f;
    #pragma unroll
    for (int ni = 0; ni < 16; ni++) {
        float a = yacc[ni][0], bb2 = yacc[ni][1];
        s0 += a + bb2; ss0 += a*a + bb2*bb2;
        float c2 = yacc[ni][2], d2 = yacc[ni][3];
        s1 += c2 + d2; ss1 += c2*c2 + d2*d2;
    }
    s0  += __shfl_xor_sync(0xffffffffu, s0, 1);
    ss0 += __shfl_xor_sync(0xffffffffu, ss0, 1);
    s1  += __shfl_xor_sync(0xffffffffu, s1, 1);
    ss1 += __shfl_xor_sync(0xffffffffu, ss1, 1);
    s0  += __shfl_xor_sync(0xffffffffu, s0, 2);
    ss0 += __shfl_xor_sync(0xffffffffu, ss0, 2);
    s1  += __shfl_xor_sync(0xffffffffu, s1, 2);
    ss1 += __shfl_xor_sync(0xffffffffu, ss1, 2);
    float mean0 = s0 * (1.0f/DHEAD);
    float var0  = ss0 * (1.0f/DHEAD) - mean0*mean0;
    float rstd0 = rsqrtf(var0 + 1e-5f);
    float mean1 = s1 * (1.0f/DHEAD);
    float var1  = ss1 * (1.0f/DHEAD) - mean1*mean1;
    float rstd1 = rsqrtf(var1 + 1e-5f);

    size_t row0off = ((size_t)(b*LSEQ + n0))*DMODEL + h*DHEAD;
    size_t row1off = ((size_t)(b*LSEQ + n1))*DMODEL + h*DHEAD;
    #pragma unroll
    for (int ni = 0; ni < 16; ni++) {
        int col = ni*8 + 2*tq;
        float2 w2 = *(const float2*)(gw + h*DHEAD + col);
        float2 b2 = *(const float2*)(gb + h*DHEAD + col);
        float2 g0 = *(const float2*)(g_G + row0off + col);
        float2 g1 = *(const float2*)(g_G + row1off + col);
        float yn00 = (yacc[ni][0] - mean0)*rstd0*w2.x + b2.x;
        float yn01 = (yacc[ni][1] - mean0)*rstd0*w2.y + b2.y;
        float yn10 = (yacc[ni][2] - mean1)*rstd1*w2.x + b2.x;
        float yn11 = (yacc[ni][3] - mean1)*rstd1*w2.y + b2.y;
        float sx00 = (g0.x / (1.0f + expf(-g0.x))) * yn00;
        float sx01 = (g0.y / (1.0f + expf(-g0.y))) * yn01;
        float sx10 = (g1.x / (1.0f + expf(-g1.x))) * yn10;
        float sx11 = (g1.y / (1.0f + expf(-g1.y))) * yn11;
        *(__half2*)(g_Sx + row0off + col) = __floats2half2_rn(sx00, sx01);
        *(__half2*)(g_Sx + row1off + col) = __floats2half2_rn(sx10, sx11);
    }
}

// ---------------- launch ----------------------------------------------------
extern "C" void kernel_launch(void* const* d_in, const int* in_sizes, int n_in,
                              void* d_out, int out_size) {
    const float* X  = (const float*)d_in[0];
    const float* WQ = (const float*)d_in[1];
    const float* WK = (const float*)d_in[2];
    const float* WV = (const float*)d_in[3];
    const float* WG = (const float*)d_in[4];
    const float* WO = (const float*)d_in[5];
    const float* gw = (const float*)d_in[6];
    const float* gb = (const float*)d_in[7];
    float* out = (float*)d_out;

    cudaFuncSetAttribute(mm_kernel, cudaFuncAttributeMaxDynamicSharedMemorySize, MM_SMEM);
    cudaFuncSetAttribute(attn_kernel, cudaFuncAttributeMaxDynamicSharedMemorySize, ATT_SMEM);

    // merged tables + X rounding
    prep_kernel<<<(MROWS*DMODEL/8)/256, 256>>>(X);
    wtrans_kernel<<<dim3(32, 160), dim3(32, 8)>>>(WQ, WK, WV, WG, WO);

    // QKV + gate projections (rotary, V transpose, raw G)
    mm_kernel<<<dim3(32, 64), 256, MM_SMEM>>>(nullptr, 0, 0);

    // retention attention + fused group norm + silu(G) gate -> Sx fp16
    attn_kernel<<<dim3(16, NHEADS, BATCH), 256, ATT_SMEM>>>(gw, gb);

    // output GEMM
    mm_kernel<<<dim3(8, 64), 256, MM_SMEM>>>(out, 2, 4096);
}